// round 1
// baseline (speedup 1.0000x reference)
#include <cuda_runtime.h>
#include <math.h>

#define BS   1024
#define NROW 512
// smem: buf0(8192 c) + buf1(8192 c) + Fc(4097 c) + TW(4097 c) + Ft(8194 f) + red(32 f)
#define SMEM_BYTES (24578*8 + 8226*4)

__device__ float g_sigma[NROW];

__device__ __forceinline__ float2 cmul(float2 a, float2 b) {
    return make_float2(a.x*b.x - a.y*b.y, a.x*b.y + a.y*b.x);
}

// One radix-4 Stockham DIF stage. m = n/4, s = 1<<ls, nbf = total/4 butterflies.
// Reads x[q + s*(p + j*m)], writes y[q + s*(4p+j)] * w^(j*p), w = exp(dir*i*2pi/n).
// Twiddle table TW[r] = (cos, sin)(2*pi*r/16384); index = p * (16384/n) = p<<jshift.
__device__ __forceinline__ void r4_stage(const float2* __restrict__ x,
                                         float2* __restrict__ y,
                                         int m, int ls, int nbf, float dir,
                                         const float2* __restrict__ TW, int jshift)
{
    const int s = 1 << ls;
    for (int id = threadIdx.x; id < nbf; id += BS) {
        const int q  = id & (s - 1);
        const int p  = id >> ls;
        const int ib = q + (p << ls);
        const int off = m << ls;
        float2 a = x[ib];
        float2 b = x[ib + off];
        float2 c = x[ib + 2*off];
        float2 d = x[ib + 3*off];
        float2 apc = make_float2(a.x + c.x, a.y + c.y);
        float2 amc = make_float2(a.x - c.x, a.y - c.y);
        float2 bpd = make_float2(b.x + d.x, b.y + d.y);
        float2 bmd = make_float2(b.x - d.x, b.y - d.y);
        // fwd (dir=-1): jb = -i*bmd ; inv (dir=+1): jb = +i*bmd
        float2 jb  = make_float2(-dir * bmd.y, dir * bmd.x);
        float2 y0 = make_float2(apc.x + bpd.x, apc.y + bpd.y);
        float2 y1 = make_float2(amc.x + jb.x,  amc.y + jb.y);
        float2 y2 = make_float2(apc.x - bpd.x, apc.y - bpd.y);
        float2 y3 = make_float2(amc.x - jb.x,  amc.y - jb.y);
        float2 t  = TW[p << jshift];
        float2 w1 = make_float2(t.x, dir * t.y);
        float2 w2 = cmul(w1, w1);
        float2 w3 = cmul(w2, w1);
        const int ob = q + ((p << 2) << ls);
        y[ob]       = y0;
        y[ob + s]   = cmul(w1, y1);
        y[ob + 2*s] = cmul(w2, y2);
        y[ob + 3*s] = cmul(w3, y3);
    }
}

// In-SMEM complex FFT of size 2^lgS (12 or 13). dir=-1 fwd, +1 inv (unnormalized).
// Stockham autosort: natural-order in, natural-order out. Returns result buffer:
// lgS=12 -> 6 stages -> original x ; lgS=13 -> 7 stages -> original y.
__device__ float2* cfft(float2* x, float2* y, int lgS, float dir, const float2* TW)
{
    int ln = lgS, ls = 0;
    const int nbf = 1 << (lgS - 2);
    while (ln >= 2) {
        r4_stage(x, y, 1 << (ln - 2), ls, nbf, dir, TW, 14 - ln);
        __syncthreads();
        float2* tmp = x; x = y; y = tmp;
        ln -= 2; ls += 2;
    }
    if (ln == 1) {   // final radix-2, s = S/2, twiddle-free
        const int half = 1 << (lgS - 1);
        for (int id = threadIdx.x; id < half; id += BS) {
            float2 a = x[id], b = x[id + half];
            y[id]        = make_float2(a.x + b.x, a.y + b.y);
            y[id + half] = make_float2(a.x - b.x, a.y - b.y);
        }
        __syncthreads();
        float2* tmp = x; x = y; y = tmp;
    }
    return x;
}

// Real-FFT unpack of a packed-complex transform Z (size Nh) at pair (k, Nh-k):
//   Bk  = V[k], Bkk = V[Nh-k]  (V = DFT_{2*Nh} of the real sequence; W = exp(-2pi*i*k/(2Nh)))
__device__ __forceinline__ void unpack_pair(float2 Zk, float2 Zkk, float2 W,
                                            float2& Bk, float2& Bkk)
{
    float2 Ze  = make_float2(0.5f*(Zk.x + Zkk.x), 0.5f*(Zk.y - Zkk.y));
    float2 Zo  = make_float2(0.5f*(Zk.y + Zkk.y), -0.5f*(Zk.x - Zkk.x));
    float2 WZo = cmul(W, Zo);
    Bk  = make_float2(Ze.x + WZo.x, Ze.y + WZo.y);
    Bkk = make_float2(Ze.x - WZo.x, WZo.y - Ze.y);   // conj(Ze - W*Zo)
}

// Repack half-spectrum pair (Uk = U[k], Ukk = U[Nh-k]) into the packed-complex
// spectrum z' that feeds the inverse CFFT_Nh.
__device__ __forceinline__ void repack_pair(float2 Uk, float2 Ukk, float2 W,
                                            float2& zk, float2& zkk)
{
    float2 Eu = make_float2(0.5f*(Uk.x + Ukk.x), 0.5f*(Uk.y - Ukk.y));
    float2 D  = make_float2(0.5f*(Uk.x - Ukk.x), 0.5f*(Uk.y + Ukk.y));
    float2 Wc = make_float2(W.x, -W.y);
    float2 Ou = cmul(D, Wc);
    zk  = make_float2(Eu.x - Ou.y, Eu.y + Ou.x);   // Eu + i*Ou
    zkk = make_float2(Eu.x + Ou.y, Ou.x - Eu.y);   // conj(Eu - i*Ou)
}

__device__ float block_reduce_sum(float v, float* red)
{
    __syncthreads();  // protect red[] from the previous use
    #pragma unroll
    for (int o = 16; o; o >>= 1) v += __shfl_down_sync(0xffffffffu, v, o);
    if ((threadIdx.x & 31) == 0) red[threadIdx.x >> 5] = v;
    __syncthreads();
    if (threadIdx.x < 32) {
        float t = red[threadIdx.x];
        #pragma unroll
        for (int o = 16; o; o >>= 1) t += __shfl_down_sync(0xffffffffu, t, o);
        if (threadIdx.x == 0) red[0] = t;
    }
    __syncthreads();
    return red[0];
}

// Fused unpack * Fc * repack, in place on Z[0..4095] (Nh=4096, N=8192).
__device__ __forceinline__ void specA(float2* Z, const float2* __restrict__ Fc,
                                      const float2* __restrict__ TW)
{
    for (int k = threadIdx.x; k <= 2048; k += BS) {
        const int kk = (4096 - k) & 4095;
        float2 t = TW[k << 1];                  // angle 2*pi*k/8192
        float2 W = make_float2(t.x, -t.y);
        float2 Bk, Bkk;
        unpack_pair(Z[k], Z[kk], W, Bk, Bkk);
        float2 Uk  = cmul(Bk,  Fc[k]);
        float2 Ukk = cmul(Bkk, Fc[4096 - k]);
        float2 zk, zkk;
        repack_pair(Uk, Ukk, W, zk, zkk);
        Z[k] = zk;
        if (k != 0) Z[kk] = zkk;
    }
}

// Fused unpack * Ft(real) * repack, in place on Z[0..8191] (Nh=8192, N=16384).
__device__ __forceinline__ void specB(float2* Z, const float* __restrict__ Ft,
                                      const float2* __restrict__ TW)
{
    for (int k = threadIdx.x; k <= 4096; k += BS) {
        const int kk = (8192 - k) & 8191;
        float2 t = TW[k];                       // angle 2*pi*k/16384
        float2 W = make_float2(t.x, -t.y);
        float2 Bk, Bkk;
        unpack_pair(Z[k], Z[kk], W, Bk, Bkk);
        const float fk  = Ft[k];
        const float fkk = Ft[8192 - k];
        float2 Uk  = make_float2(Bk.x * fk,  Bk.y * fk);
        float2 Ukk = make_float2(Bkk.x * fkk, Bkk.y * fkk);
        float2 zk, zkk;
        repack_pair(Uk, Ukk, W, zk, zkk);
        Z[k] = zk;
        if (k != 0) Z[kk] = zkk;
    }
}

__global__ void __launch_bounds__(BS)
power_kernel(const float* __restrict__ gx, const float* __restrict__ gc,
             const float* __restrict__ gb0)
{
    extern __shared__ float2 smem2[];
    float2* buf0 = smem2;               // 8192
    float2* buf1 = smem2 + 8192;        // 8192
    float2* Fc   = smem2 + 16384;       // 4097  : DFT_8192(circ)/4096, k=0..4096
    float2* TW   = smem2 + 20481;       // 4097  : (cos,sin)(2*pi*r/16384), r=0..4096
    float*  Ft   = (float*)(smem2 + 24578); // 8194 : Re(DFT_16384(embed))/8192, k=0..8192
    float*  red  = Ft + 8194;           // 32

    const int tid = threadIdx.x;
    const int row = blockIdx.x;
    const float* xr = gx  + (size_t)row * 8192;
    const float* cr = gc  + (size_t)row * 8192;
    const float* br = gb0 + (size_t)row * 8192;

    // ---- twiddle table ----
    for (int r = tid; r <= 4096; r += BS) {
        float sv, cv;
        sincospif((float)r * (1.0f / 8192.0f), &sv, &cv);
        TW[r] = make_float2(cv, sv);
    }
    __syncthreads();

    // ---- Fc = DFT_8192(circ) / 4096 (half spectrum) ----
    for (int n = tid; n < 4096; n += BS)
        buf0[n] = make_float2(cr[2*n], cr[2*n + 1]);
    __syncthreads();
    {
        float2* Z = cfft(buf0, buf1, 12, -1.0f, TW);    // == buf0
        const float sc = 1.0f / 4096.0f;
        for (int k = tid; k <= 2048; k += BS) {
            const int kk = (4096 - k) & 4095;
            float2 t = TW[k << 1];
            float2 W = make_float2(t.x, -t.y);
            float2 Bk, Bkk;
            unpack_pair(Z[k], Z[kk], W, Bk, Bkk);
            Fc[k]        = make_float2(Bk.x * sc,  Bk.y * sc);
            Fc[4096 - k] = make_float2(Bkk.x * sc, Bkk.y * sc);
        }
    }
    __syncthreads();

    // ---- Ft = Re(DFT_16384([x, 0, flip(x[1:])])) / 8192 (half spectrum, real) ----
    for (int n = tid; n < 8192; n += BS) {
        const int j0 = 2*n, j1 = 2*n + 1;
        float e0 = (j0 < 8192) ? xr[j0] : ((j0 == 8192) ? 0.0f : xr[16384 - j0]);
        float e1 = (j1 < 8192) ? xr[j1] : xr[16384 - j1];
        buf0[n] = make_float2(e0, e1);
    }
    __syncthreads();
    {
        float2* Z = cfft(buf0, buf1, 13, -1.0f, TW);    // == buf1
        const float sc = 1.0f / 8192.0f;
        for (int k = tid; k <= 4096; k += BS) {
            const int kk = (8192 - k) & 8191;
            float2 t = TW[k];
            float2 W = make_float2(t.x, -t.y);
            float2 Bk, Bkk;
            unpack_pair(Z[k], Z[kk], W, Bk, Bkk);
            Ft[k]        = Bk.x * sc;
            Ft[8192 - k] = Bkk.x * sc;
        }
    }
    __syncthreads();

    // ---- b = b0 / ||b0||, thread t owns b[8t .. 8t+7] ----
    float b[8];
    {
        const float4 v0 = *(const float4*)(br + tid*8);
        const float4 v1 = *(const float4*)(br + tid*8 + 4);
        b[0]=v0.x; b[1]=v0.y; b[2]=v0.z; b[3]=v0.w;
        b[4]=v1.x; b[5]=v1.y; b[6]=v1.z; b[7]=v1.w;
        float ss = 0.0f;
        #pragma unroll
        for (int i = 0; i < 8; i++) ss += b[i]*b[i];
        float tot = block_reduce_sum(ss, red);
        float inv = 1.0f / sqrtf(tot);
        #pragma unroll
        for (int i = 0; i < 8; i++) b[i] *= inv;
    }

    // ---- 100 power iterations + 1 final application ----
    for (int it = 0; it <= 100; ++it) {
        // pack b: buf0[n] = (b[2n], b[2n+1]), n = 4*tid + j
        #pragma unroll
        for (int j = 0; j < 4; ++j)
            buf0[4*tid + j] = make_float2(b[2*j], b[2*j + 1]);
        __syncthreads();

        // u = IFFT( Fc * FFT(b) )   (8192-point real conv via 4096-pt CFFT)
        cfft(buf0, buf1, 12, -1.0f, TW);        // -> buf0
        specA(buf0, Fc, TW);
        __syncthreads();
        cfft(buf0, buf1, 12, +1.0f, TW);        // -> buf0 : packed u

        // zero-pad upper half for the 16384-point transform
        for (int n = 4096 + tid; n < 8192; n += BS)
            buf0[n] = make_float2(0.0f, 0.0f);
        __syncthreads();

        // w = first 8192 of IFFT_16384( Ft * FFT_16384([u,0]) )
        cfft(buf0, buf1, 13, -1.0f, TW);        // -> buf1
        specB(buf1, Ft, TW);
        __syncthreads();
        cfft(buf1, buf0, 13, +1.0f, TW);        // -> buf0 : packed w

        float w_[8];
        #pragma unroll
        for (int j = 0; j < 4; ++j) {
            float2 v = buf0[4*tid + j];
            w_[2*j]     = v.x;
            w_[2*j + 1] = v.y;
        }

        if (it < 100) {
            float nb[8];
            float ss = 0.0f;
            #pragma unroll
            for (int i = 0; i < 8; i++) { nb[i] = b[i] - w_[i]; ss += nb[i]*nb[i]; }
            float tot = block_reduce_sum(ss, red);
            float inv = 1.0f / sqrtf(tot);
            #pragma unroll
            for (int i = 0; i < 8; i++) b[i] = nb[i] * inv;
        } else {
            float dp = 0.0f;
            #pragma unroll
            for (int i = 0; i < 8; i++) dp += b[i] * w_[i];
            float tot = block_reduce_sum(dp, red);
            if (tid == 0) g_sigma[row] = 1.0f - tot;   // sigma = b.(b - w) = 1 - b.w
        }
    }
}

__global__ void finalize_kernel(float* __restrict__ out)
{
    __shared__ float red[16];
    const int t = threadIdx.x;   // 512 threads
    float v = fabsf(g_sigma[t]);
    #pragma unroll
    for (int o = 16; o; o >>= 1) v += __shfl_down_sync(0xffffffffu, v, o);
    if ((t & 31) == 0) red[t >> 5] = v;
    __syncthreads();
    if (t < 16) {
        float s = red[t];
        #pragma unroll
        for (int o = 8; o; o >>= 1) s += __shfl_down_sync(0xffffu, s, o);
        if (t == 0) out[0] = s * (1.0f / 512.0f);
    }
}

extern "C" void kernel_launch(void* const* d_in, const int* in_sizes, int n_in,
                              void* d_out, int out_size)
{
    (void)in_sizes; (void)n_in; (void)out_size;
    const float* x    = (const float*)d_in[0];
    const float* circ = (const float*)d_in[1];
    const float* b0   = (const float*)d_in[2];

    cudaFuncSetAttribute(power_kernel,
                         cudaFuncAttributeMaxDynamicSharedMemorySize, SMEM_BYTES);
    power_kernel<<<NROW, BS, SMEM_BYTES>>>(x, circ, b0);
    finalize_kernel<<<1, 512>>>((float*)d_out);
}

// round 2
// speedup vs baseline: 1.0002x; 1.0002x over previous
#include <cuda_runtime.h>
#include <math.h>

#define BS   1024
#define NROW 512
// smem: buf0(8192 c) + buf1(8192 c) + Fc(4097 c) + TW(4097 c) + Ft(8194 f) + red(32 f)
#define SMEM_BYTES (24578*8 + 8226*4)

__device__ float g_sigma[NROW];

__device__ __forceinline__ float2 cmul(float2 a, float2 b) {
    return make_float2(a.x*b.x - a.y*b.y, a.x*b.y + a.y*b.x);
}

// One radix-4 Stockham DIF stage. m = n/4, s = 1<<ls, nbf = total/4 butterflies.
// Reads x[q + s*(p + j*m)], writes y[q + s*(4p+j)] * w^(j*p), w = exp(dir*i*2pi/n).
// Twiddle table TW[r] = (cos, sin)(2*pi*r/16384); index = p * (16384/n) = p<<jshift.
__device__ __forceinline__ void r4_stage(const float2* __restrict__ x,
                                         float2* __restrict__ y,
                                         int m, int ls, int nbf, float dir,
                                         const float2* __restrict__ TW, int jshift)
{
    const int s = 1 << ls;
    for (int id = threadIdx.x; id < nbf; id += BS) {
        const int q  = id & (s - 1);
        const int p  = id >> ls;
        const int ib = q + (p << ls);
        const int off = m << ls;
        float2 a = x[ib];
        float2 b = x[ib + off];
        float2 c = x[ib + 2*off];
        float2 d = x[ib + 3*off];
        float2 apc = make_float2(a.x + c.x, a.y + c.y);
        float2 amc = make_float2(a.x - c.x, a.y - c.y);
        float2 bpd = make_float2(b.x + d.x, b.y + d.y);
        float2 bmd = make_float2(b.x - d.x, b.y - d.y);
        // fwd (dir=-1): jb = -i*bmd ; inv (dir=+1): jb = +i*bmd
        float2 jb  = make_float2(-dir * bmd.y, dir * bmd.x);
        float2 y0 = make_float2(apc.x + bpd.x, apc.y + bpd.y);
        float2 y1 = make_float2(amc.x + jb.x,  amc.y + jb.y);
        float2 y2 = make_float2(apc.x - bpd.x, apc.y - bpd.y);
        float2 y3 = make_float2(amc.x - jb.x,  amc.y - jb.y);
        float2 t  = TW[p << jshift];
        float2 w1 = make_float2(t.x, dir * t.y);
        float2 w2 = cmul(w1, w1);
        float2 w3 = cmul(w2, w1);
        const int ob = q + ((p << 2) << ls);
        y[ob]       = y0;
        y[ob + s]   = cmul(w1, y1);
        y[ob + 2*s] = cmul(w2, y2);
        y[ob + 3*s] = cmul(w3, y3);
    }
}

// In-SMEM complex FFT of size 2^lgS (12 or 13). dir=-1 fwd, +1 inv (unnormalized).
// Stockham autosort: natural-order in, natural-order out. Returns result buffer:
// lgS=12 -> 6 stages -> original x ; lgS=13 -> 7 stages -> original y.
__device__ float2* cfft(float2* x, float2* y, int lgS, float dir, const float2* TW)
{
    int ln = lgS, ls = 0;
    const int nbf = 1 << (lgS - 2);
    while (ln >= 2) {
        r4_stage(x, y, 1 << (ln - 2), ls, nbf, dir, TW, 14 - ln);
        __syncthreads();
        float2* tmp = x; x = y; y = tmp;
        ln -= 2; ls += 2;
    }
    if (ln == 1) {   // final radix-2, s = S/2, twiddle-free
        const int half = 1 << (lgS - 1);
        for (int id = threadIdx.x; id < half; id += BS) {
            float2 a = x[id], b = x[id + half];
            y[id]        = make_float2(a.x + b.x, a.y + b.y);
            y[id + half] = make_float2(a.x - b.x, a.y - b.y);
        }
        __syncthreads();
        float2* tmp = x; x = y; y = tmp;
    }
    return x;
}

// Real-FFT unpack of a packed-complex transform Z (size Nh) at pair (k, Nh-k):
//   Bk  = V[k], Bkk = V[Nh-k]  (V = DFT_{2*Nh} of the real sequence; W = exp(-2pi*i*k/(2Nh)))
__device__ __forceinline__ void unpack_pair(float2 Zk, float2 Zkk, float2 W,
                                            float2& Bk, float2& Bkk)
{
    float2 Ze  = make_float2(0.5f*(Zk.x + Zkk.x), 0.5f*(Zk.y - Zkk.y));
    float2 Zo  = make_float2(0.5f*(Zk.y + Zkk.y), -0.5f*(Zk.x - Zkk.x));
    float2 WZo = cmul(W, Zo);
    Bk  = make_float2(Ze.x + WZo.x, Ze.y + WZo.y);
    Bkk = make_float2(Ze.x - WZo.x, WZo.y - Ze.y);   // conj(Ze - W*Zo)
}

// Repack half-spectrum pair (Uk = U[k], Ukk = U[Nh-k]) into the packed-complex
// spectrum z' that feeds the inverse CFFT_Nh.
__device__ __forceinline__ void repack_pair(float2 Uk, float2 Ukk, float2 W,
                                            float2& zk, float2& zkk)
{
    float2 Eu = make_float2(0.5f*(Uk.x + Ukk.x), 0.5f*(Uk.y - Ukk.y));
    float2 D  = make_float2(0.5f*(Uk.x - Ukk.x), 0.5f*(Uk.y + Ukk.y));
    float2 Wc = make_float2(W.x, -W.y);
    float2 Ou = cmul(D, Wc);
    zk  = make_float2(Eu.x - Ou.y, Eu.y + Ou.x);   // Eu + i*Ou
    zkk = make_float2(Eu.x + Ou.y, Ou.x - Eu.y);   // conj(Eu - i*Ou)
}

__device__ float block_reduce_sum(float v, float* red)
{
    __syncthreads();  // protect red[] from the previous use
    #pragma unroll
    for (int o = 16; o; o >>= 1) v += __shfl_down_sync(0xffffffffu, v, o);
    if ((threadIdx.x & 31) == 0) red[threadIdx.x >> 5] = v;
    __syncthreads();
    if (threadIdx.x < 32) {
        float t = red[threadIdx.x];
        #pragma unroll
        for (int o = 16; o; o >>= 1) t += __shfl_down_sync(0xffffffffu, t, o);
        if (threadIdx.x == 0) red[0] = t;
    }
    __syncthreads();
    return red[0];
}

// Fused unpack * Fc * repack, in place on Z[0..4095] (Nh=4096, N=8192).
__device__ __forceinline__ void specA(float2* Z, const float2* __restrict__ Fc,
                                      const float2* __restrict__ TW)
{
    for (int k = threadIdx.x; k <= 2048; k += BS) {
        const int kk = (4096 - k) & 4095;
        float2 t = TW[k << 1];                  // angle 2*pi*k/8192
        float2 W = make_float2(t.x, -t.y);
        float2 Bk, Bkk;
        unpack_pair(Z[k], Z[kk], W, Bk, Bkk);
        float2 Uk  = cmul(Bk,  Fc[k]);
        float2 Ukk = cmul(Bkk, Fc[4096 - k]);
        float2 zk, zkk;
        repack_pair(Uk, Ukk, W, zk, zkk);
        Z[k] = zk;
        if (k != 0) Z[kk] = zkk;
    }
}

// Fused unpack * Ft(real) * repack, in place on Z[0..8191] (Nh=8192, N=16384).
__device__ __forceinline__ void specB(float2* Z, const float* __restrict__ Ft,
                                      const float2* __restrict__ TW)
{
    for (int k = threadIdx.x; k <= 4096; k += BS) {
        const int kk = (8192 - k) & 8191;
        float2 t = TW[k];                       // angle 2*pi*k/16384
        float2 W = make_float2(t.x, -t.y);
        float2 Bk, Bkk;
        unpack_pair(Z[k], Z[kk], W, Bk, Bkk);
        const float fk  = Ft[k];
        const float fkk = Ft[8192 - k];
        float2 Uk  = make_float2(Bk.x * fk,  Bk.y * fk);
        float2 Ukk = make_float2(Bkk.x * fkk, Bkk.y * fkk);
        float2 zk, zkk;
        repack_pair(Uk, Ukk, W, zk, zkk);
        Z[k] = zk;
        if (k != 0) Z[kk] = zkk;
    }
}

__global__ void __launch_bounds__(BS)
power_kernel(const float* __restrict__ gx, const float* __restrict__ gc,
             const float* __restrict__ gb0)
{
    extern __shared__ float2 smem2[];
    float2* buf0 = smem2;               // 8192
    float2* buf1 = smem2 + 8192;        // 8192
    float2* Fc   = smem2 + 16384;       // 4097  : DFT_8192(circ)/4096, k=0..4096
    float2* TW   = smem2 + 20481;       // 4097  : (cos,sin)(2*pi*r/16384), r=0..4096
    float*  Ft   = (float*)(smem2 + 24578); // 8194 : Re(DFT_16384(embed))/8192, k=0..8192
    float*  red  = Ft + 8194;           // 32

    const int tid = threadIdx.x;
    const int row = blockIdx.x;
    const float* xr = gx  + (size_t)row * 8192;
    const float* cr = gc  + (size_t)row * 8192;
    const float* br = gb0 + (size_t)row * 8192;

    // ---- twiddle table ----
    for (int r = tid; r <= 4096; r += BS) {
        float sv, cv;
        sincospif((float)r * (1.0f / 8192.0f), &sv, &cv);
        TW[r] = make_float2(cv, sv);
    }
    __syncthreads();

    // ---- Fc = DFT_8192(circ) / 4096 (half spectrum) ----
    for (int n = tid; n < 4096; n += BS)
        buf0[n] = make_float2(cr[2*n], cr[2*n + 1]);
    __syncthreads();
    {
        float2* Z = cfft(buf0, buf1, 12, -1.0f, TW);    // == buf0
        const float sc = 1.0f / 4096.0f;
        for (int k = tid; k <= 2048; k += BS) {
            const int kk = (4096 - k) & 4095;
            float2 t = TW[k << 1];
            float2 W = make_float2(t.x, -t.y);
            float2 Bk, Bkk;
            unpack_pair(Z[k], Z[kk], W, Bk, Bkk);
            Fc[k]        = make_float2(Bk.x * sc,  Bk.y * sc);
            Fc[4096 - k] = make_float2(Bkk.x * sc, Bkk.y * sc);
        }
    }
    __syncthreads();

    // ---- Ft = Re(DFT_16384([x, 0, flip(x[1:])])) / 8192 (half spectrum, real) ----
    for (int n = tid; n < 8192; n += BS) {
        const int j0 = 2*n, j1 = 2*n + 1;
        float e0 = (j0 < 8192) ? xr[j0] : ((j0 == 8192) ? 0.0f : xr[16384 - j0]);
        float e1 = (j1 < 8192) ? xr[j1] : xr[16384 - j1];
        buf0[n] = make_float2(e0, e1);
    }
    __syncthreads();
    {
        float2* Z = cfft(buf0, buf1, 13, -1.0f, TW);    // == buf1
        const float sc = 1.0f / 8192.0f;
        for (int k = tid; k <= 4096; k += BS) {
            const int kk = (8192 - k) & 8191;
            float2 t = TW[k];
            float2 W = make_float2(t.x, -t.y);
            float2 Bk, Bkk;
            unpack_pair(Z[k], Z[kk], W, Bk, Bkk);
            Ft[k]        = Bk.x * sc;
            Ft[8192 - k] = Bkk.x * sc;
        }
    }
    __syncthreads();

    // ---- b = b0 / ||b0||, thread t owns b[8t .. 8t+7] ----
    float b[8];
    {
        const float4 v0 = *(const float4*)(br + tid*8);
        const float4 v1 = *(const float4*)(br + tid*8 + 4);
        b[0]=v0.x; b[1]=v0.y; b[2]=v0.z; b[3]=v0.w;
        b[4]=v1.x; b[5]=v1.y; b[6]=v1.z; b[7]=v1.w;
        float ss = 0.0f;
        #pragma unroll
        for (int i = 0; i < 8; i++) ss += b[i]*b[i];
        float tot = block_reduce_sum(ss, red);
        float inv = 1.0f / sqrtf(tot);
        #pragma unroll
        for (int i = 0; i < 8; i++) b[i] *= inv;
    }

    // ---- 100 power iterations + 1 final application ----
    for (int it = 0; it <= 100; ++it) {
        // pack b: buf0[n] = (b[2n], b[2n+1]), n = 4*tid + j
        #pragma unroll
        for (int j = 0; j < 4; ++j)
            buf0[4*tid + j] = make_float2(b[2*j], b[2*j + 1]);
        __syncthreads();

        // u = IFFT( Fc * FFT(b) )   (8192-point real conv via 4096-pt CFFT)
        cfft(buf0, buf1, 12, -1.0f, TW);        // -> buf0
        specA(buf0, Fc, TW);
        __syncthreads();
        cfft(buf0, buf1, 12, +1.0f, TW);        // -> buf0 : packed u

        // zero-pad upper half for the 16384-point transform
        for (int n = 4096 + tid; n < 8192; n += BS)
            buf0[n] = make_float2(0.0f, 0.0f);
        __syncthreads();

        // w = first 8192 of IFFT_16384( Ft * FFT_16384([u,0]) )
        cfft(buf0, buf1, 13, -1.0f, TW);        // -> buf1
        specB(buf1, Ft, TW);
        __syncthreads();
        cfft(buf1, buf0, 13, +1.0f, TW);        // -> buf0 : packed w

        float w_[8];
        #pragma unroll
        for (int j = 0; j < 4; ++j) {
            float2 v = buf0[4*tid + j];
            w_[2*j]     = v.x;
            w_[2*j + 1] = v.y;
        }

        if (it < 100) {
            float nb[8];
            float ss = 0.0f;
            #pragma unroll
            for (int i = 0; i < 8; i++) { nb[i] = b[i] - w_[i]; ss += nb[i]*nb[i]; }
            float tot = block_reduce_sum(ss, red);
            float inv = 1.0f / sqrtf(tot);
            #pragma unroll
            for (int i = 0; i < 8; i++) b[i] = nb[i] * inv;
        } else {
            float dp = 0.0f;
            #pragma unroll
            for (int i = 0; i < 8; i++) dp += b[i] * w_[i];
            float tot = block_reduce_sum(dp, red);
            if (tid == 0) g_sigma[row] = 1.0f - tot;   // sigma = b.(b - w) = 1 - b.w
        }
    }
}

__global__ void finalize_kernel(float* __restrict__ out)
{
    __shared__ float red[16];
    const int t = threadIdx.x;   // 512 threads
    float v = fabsf(g_sigma[t]);
    #pragma unroll
    for (int o = 16; o; o >>= 1) v += __shfl_down_sync(0xffffffffu, v, o);
    if ((t & 31) == 0) red[t >> 5] = v;
    __syncthreads();
    if (t < 16) {
        float s = red[t];
        #pragma unroll
        for (int o = 8; o; o >>= 1) s += __shfl_down_sync(0xffffu, s, o);
        if (t == 0) out[0] = s * (1.0f / 512.0f);
    }
}

extern "C" void kernel_launch(void* const* d_in, const int* in_sizes, int n_in,
                              void* d_out, int out_size)
{
    (void)in_sizes; (void)n_in; (void)out_size;
    const float* x    = (const float*)d_in[0];
    const float* circ = (const float*)d_in[1];
    const float* b0   = (const float*)d_in[2];

    cudaFuncSetAttribute(power_kernel,
                         cudaFuncAttributeMaxDynamicSharedMemorySize, SMEM_BYTES);
    power_kernel<<<NROW, BS, SMEM_BYTES>>>(x, circ, b0);
    finalize_kernel<<<1, 512>>>((float*)d_out);
}

// round 3
// speedup vs baseline: 1.8130x; 1.8126x over previous
#include <cuda_runtime.h>
#include <math.h>

#define BS   512
#define NROW 512
// smem: buf0(8192 c) + buf1(8192 c) + Fc(4097 c) + TW(4097 c) + Ft(8194 f) + red(32 f)
#define SMEM_BYTES (24578*8 + 8226*4)

__device__ float g_sigma[NROW];

__device__ __forceinline__ int SW(int i) { return i ^ ((i >> 5) & 31); }

__device__ __forceinline__ float2 cmul(float2 a, float2 b) {
    return make_float2(a.x*b.x - a.y*b.y, a.x*b.y + a.y*b.x);
}

// 4-point DFT in registers. Y_j = sum_r x_r * exp(DIR*2pi*i*j*r/4).
template<int DIR>
__device__ __forceinline__ void dft4i(float2& a, float2& b, float2& c, float2& d) {
    float2 apc = make_float2(a.x + c.x, a.y + c.y);
    float2 amc = make_float2(a.x - c.x, a.y - c.y);
    float2 bpd = make_float2(b.x + d.x, b.y + d.y);
    float2 bmd = make_float2(b.x - d.x, b.y - d.y);
    float2 jb;   // DIR * i * bmd
    if (DIR > 0) jb = make_float2(-bmd.y,  bmd.x);
    else         jb = make_float2( bmd.y, -bmd.x);
    a = make_float2(apc.x + bpd.x, apc.y + bpd.y);
    b = make_float2(amc.x + jb.x,  amc.y + jb.y);
    c = make_float2(apc.x - bpd.x, apc.y - bpd.y);
    d = make_float2(amc.x - jb.x,  amc.y - jb.y);
}

// Internal W16 twiddles for the 16-pt DFT: v[b+4c] *= exp(DIR*2pi*i*b*c/16)
template<int DIR>
__device__ __forceinline__ void applyW16(float2* v) {
    const float C1 = 0.9238795325112867f, S1 = 0.3826834323650898f;
    const float H  = 0.7071067811865476f;
    const float D  = (DIR > 0) ? 1.0f : -1.0f;
    v[5]  = cmul(v[5],  make_float2( C1,  D*S1));   // t=1
    v[9]  = cmul(v[9],  make_float2(  H,  D*H));    // t=2
    v[13] = cmul(v[13], make_float2( S1,  D*C1));   // t=3
    v[6]  = cmul(v[6],  make_float2(  H,  D*H));    // t=2
    v[10] = cmul(v[10], make_float2(0.f,  D*1.f));  // t=4
    v[14] = cmul(v[14], make_float2( -H,  D*H));    // t=6
    v[7]  = cmul(v[7],  make_float2( S1,  D*C1));   // t=3
    v[11] = cmul(v[11], make_float2( -H,  D*H));    // t=6
    v[15] = cmul(v[15], make_float2(-C1, -D*S1));   // t=9
}

// One radix-16 Stockham round. Gathers x[ib + r*off] (r=0..15), 16-pt DFT in
// registers, applies W_ln^{j*p}, scatters y[ob + j*s].
// off = m*s = S/16 (constant per FFT size). If ZHI, inputs r>=8 are zero
// (fused zero-padding; only valid for the s=1 round of the 8192 FFT).
template<int DIR, bool ZHI>
__device__ __forceinline__ void r16_round(const float2* __restrict__ x,
                                          float2* __restrict__ y,
                                          int lgln, int ls,
                                          const float2* __restrict__ TW,
                                          int nbf, int off)
{
    const int s = 1 << ls;
    for (int id = threadIdx.x; id < nbf; id += BS) {
        const int q  = id & (s - 1);
        const int p  = id >> ls;
        const int ib = q + (p << ls);
        float2 v[16];
        #pragma unroll
        for (int r = 0; r < 16; r++) {
            if (ZHI && r >= 8) v[r] = make_float2(0.f, 0.f);
            else               v[r] = x[SW(ib + r * off)];
        }
        // step 1: DFT4 over a for each b  (x_{4a+b} -> A_b(c) at v[b+4c])
        #pragma unroll
        for (int bb = 0; bb < 4; bb++)
            dft4i<DIR>(v[bb], v[bb+4], v[bb+8], v[bb+12]);
        applyW16<DIR>(v);
        // step 2: DFT4 over b within each group of 4 (X_{c+4d} at v[4c+d])
        #pragma unroll
        for (int c = 0; c < 4; c++)
            dft4i<DIR>(v[4*c], v[4*c+1], v[4*c+2], v[4*c+3]);
        // stage twiddle W_ln^{j*p} and scatter (j = c + 4d <-> slot v[4c+d])
        float2 t  = TW[p << (14 - lgln)];
        float2 w1 = make_float2(t.x, (DIR > 0) ? t.y : -t.y);
        float2 w2 = cmul(w1, w1);
        float2 w3 = cmul(w2, w1);
        float2 w4 = cmul(w2, w2);
        const int ob = q + ((p << 4) << ls);
        y[SW(ob)]         = v[0];
        y[SW(ob + s)]     = cmul(w1, v[4]);
        y[SW(ob + 2*s)]   = cmul(w2, v[8]);
        y[SW(ob + 3*s)]   = cmul(w3, v[12]);
        float2 wr = w4;
        #pragma unroll
        for (int d = 1; d < 4; d++) {
            const int jb = 4 * d;
            y[SW(ob + (jb    )*s)] = cmul(wr, v[d]);
            y[SW(ob + (jb + 1)*s)] = cmul(cmul(wr, w1), v[4 + d]);
            y[SW(ob + (jb + 2)*s)] = cmul(cmul(wr, w2), v[8 + d]);
            y[SW(ob + (jb + 3)*s)] = cmul(cmul(wr, w3), v[12 + d]);
            if (d < 3) wr = cmul(wr, w4);
        }
    }
}

// Final twiddle-free radix-2 round for the 8192 FFT (s = 4096).
__device__ __forceinline__ void r2_round(const float2* __restrict__ x,
                                         float2* __restrict__ y, bool half)
{
    for (int id = threadIdx.x; id < 4096; id += BS) {
        float2 a = x[SW(id)], b = x[SW(id + 4096)];
        y[SW(id)] = make_float2(a.x + b.x, a.y + b.y);
        if (!half) y[SW(id + 4096)] = make_float2(a.x - b.x, a.y - b.y);
    }
}

// 4096-pt complex FFT: 3 radix-16 rounds. Input x, result lands in y.
template<int DIR>
__device__ void cfft4096(float2* x, float2* y, const float2* TW)
{
    r16_round<DIR,false>(x, y, 12, 0, TW, 256, 256); __syncthreads();
    r16_round<DIR,false>(y, x,  8, 4, TW, 256, 256); __syncthreads();
    r16_round<DIR,false>(x, y,  4, 8, TW, 256, 256); __syncthreads();
}

// 8192-pt complex FFT: 3 radix-16 rounds + final radix-2. Result lands in x.
// ZHI: treat x[4096..8191] as zero in round 1. half_last: only store the
// lower 4096 outputs of the final round.
template<int DIR, bool ZHI>
__device__ void cfft8192(float2* x, float2* y, const float2* TW, bool half_last)
{
    r16_round<DIR,ZHI  >(x, y, 13, 0, TW, 512, 512); __syncthreads();
    r16_round<DIR,false>(y, x,  9, 4, TW, 512, 512); __syncthreads();
    r16_round<DIR,false>(x, y,  5, 8, TW, 512, 512); __syncthreads();
    r2_round(y, x, half_last);                        __syncthreads();
}

// Real-FFT unpack: Bk = V[k], Bkk = V[Nh-k] from packed transform Z.
__device__ __forceinline__ void unpack_pair(float2 Zk, float2 Zkk, float2 W,
                                            float2& Bk, float2& Bkk)
{
    float2 Ze  = make_float2(0.5f*(Zk.x + Zkk.x), 0.5f*(Zk.y - Zkk.y));
    float2 Zo  = make_float2(0.5f*(Zk.y + Zkk.y), -0.5f*(Zk.x - Zkk.x));
    float2 WZo = cmul(W, Zo);
    Bk  = make_float2(Ze.x + WZo.x, Ze.y + WZo.y);
    Bkk = make_float2(Ze.x - WZo.x, WZo.y - Ze.y);
}

__device__ __forceinline__ void repack_pair(float2 Uk, float2 Ukk, float2 W,
                                            float2& zk, float2& zkk)
{
    float2 Eu = make_float2(0.5f*(Uk.x + Ukk.x), 0.5f*(Uk.y - Ukk.y));
    float2 D  = make_float2(0.5f*(Uk.x - Ukk.x), 0.5f*(Uk.y + Ukk.y));
    float2 Wc = make_float2(W.x, -W.y);
    float2 Ou = cmul(D, Wc);
    zk  = make_float2(Eu.x - Ou.y, Eu.y + Ou.x);
    zkk = make_float2(Eu.x + Ou.y, Ou.x - Eu.y);
}

__device__ float block_reduce_sum(float v, float* red)
{
    __syncthreads();
    #pragma unroll
    for (int o = 16; o; o >>= 1) v += __shfl_down_sync(0xffffffffu, v, o);
    if ((threadIdx.x & 31) == 0) red[threadIdx.x >> 5] = v;
    __syncthreads();
    if (threadIdx.x < 32) {
        float t = (threadIdx.x < 16) ? red[threadIdx.x] : 0.0f;
        #pragma unroll
        for (int o = 8; o; o >>= 1) t += __shfl_down_sync(0xffffffffu, t, o);
        if (threadIdx.x == 0) red[0] = t;
    }
    __syncthreads();
    return red[0];
}

// Fused unpack * Fc * repack, in place on Z[0..4095] (Nh=4096, N=8192).
__device__ __forceinline__ void specA(float2* Z, const float2* __restrict__ Fc,
                                      const float2* __restrict__ TW)
{
    for (int k = threadIdx.x; k <= 2048; k += BS) {
        const int kk = (4096 - k) & 4095;
        float2 t = TW[k << 1];
        float2 W = make_float2(t.x, -t.y);
        float2 Bk, Bkk;
        unpack_pair(Z[SW(k)], Z[SW(kk)], W, Bk, Bkk);
        float2 Uk  = cmul(Bk,  Fc[k]);
        float2 Ukk = cmul(Bkk, Fc[4096 - k]);
        float2 zk, zkk;
        repack_pair(Uk, Ukk, W, zk, zkk);
        Z[SW(k)] = zk;
        if (k != 0) Z[SW(kk)] = zkk;
    }
}

// Fused unpack * Ft(real) * repack, in place on Z[0..8191] (Nh=8192, N=16384).
__device__ __forceinline__ void specB(float2* Z, const float* __restrict__ Ft,
                                      const float2* __restrict__ TW)
{
    for (int k = threadIdx.x; k <= 4096; k += BS) {
        const int kk = (8192 - k) & 8191;
        float2 t = TW[k];
        float2 W = make_float2(t.x, -t.y);
        float2 Bk, Bkk;
        unpack_pair(Z[SW(k)], Z[SW(kk)], W, Bk, Bkk);
        const float fk  = Ft[k];
        const float fkk = Ft[8192 - k];
        float2 Uk  = make_float2(Bk.x * fk,  Bk.y * fk);
        float2 Ukk = make_float2(Bkk.x * fkk, Bkk.y * fkk);
        float2 zk, zkk;
        repack_pair(Uk, Ukk, W, zk, zkk);
        Z[SW(k)] = zk;
        if (k != 0) Z[SW(kk)] = zkk;
    }
}

__global__ void __launch_bounds__(BS)
power_kernel(const float* __restrict__ gx, const float* __restrict__ gc,
             const float* __restrict__ gb0)
{
    extern __shared__ float2 smem2[];
    float2* buf0 = smem2;               // 8192
    float2* buf1 = smem2 + 8192;        // 8192
    float2* Fc   = smem2 + 16384;       // 4097
    float2* TW   = smem2 + 20481;       // 4097 : (cos,sin)(2*pi*r/16384)
    float*  Ft   = (float*)(smem2 + 24578); // 8194
    float*  red  = Ft + 8194;           // 32

    const int tid = threadIdx.x;
    const int row = blockIdx.x;
    const float* xr = gx  + (size_t)row * 8192;
    const float* cr = gc  + (size_t)row * 8192;
    const float* br = gb0 + (size_t)row * 8192;

    // ---- twiddle table ----
    for (int r = tid; r <= 4096; r += BS) {
        float sv, cv;
        sincospif((float)r * (1.0f / 8192.0f), &sv, &cv);
        TW[r] = make_float2(cv, sv);
    }
    __syncthreads();

    // ---- Fc = DFT_8192(circ) / 4096 (half spectrum) ----
    for (int n = tid; n < 4096; n += BS)
        buf0[SW(n)] = make_float2(cr[2*n], cr[2*n + 1]);
    __syncthreads();
    cfft4096<-1>(buf0, buf1, TW);                 // result in buf1
    {
        float2* Z = buf1;
        const float sc = 1.0f / 4096.0f;
        for (int k = tid; k <= 2048; k += BS) {
            const int kk = (4096 - k) & 4095;
            float2 t = TW[k << 1];
            float2 W = make_float2(t.x, -t.y);
            float2 Bk, Bkk;
            unpack_pair(Z[SW(k)], Z[SW(kk)], W, Bk, Bkk);
            Fc[k]        = make_float2(Bk.x * sc,  Bk.y * sc);
            Fc[4096 - k] = make_float2(Bkk.x * sc, Bkk.y * sc);
        }
    }
    __syncthreads();

    // ---- Ft = Re(DFT_16384([x, 0, flip(x[1:])])) / 8192 (real half spectrum) ----
    for (int n = tid; n < 8192; n += BS) {
        const int j0 = 2*n, j1 = 2*n + 1;
        float e0 = (j0 < 8192) ? xr[j0] : ((j0 == 8192) ? 0.0f : xr[16384 - j0]);
        float e1 = (j1 < 8192) ? xr[j1] : xr[16384 - j1];
        buf0[SW(n)] = make_float2(e0, e1);
    }
    __syncthreads();
    cfft8192<-1,false>(buf0, buf1, TW, false);    // result in buf0
    {
        float2* Z = buf0;
        const float sc = 1.0f / 8192.0f;
        for (int k = tid; k <= 4096; k += BS) {
            const int kk = (8192 - k) & 8191;
            float2 t = TW[k];
            float2 W = make_float2(t.x, -t.y);
            float2 Bk, Bkk;
            unpack_pair(Z[SW(k)], Z[SW(kk)], W, Bk, Bkk);
            Ft[k]        = Bk.x * sc;
            Ft[8192 - k] = Bkk.x * sc;
        }
    }
    __syncthreads();

    // ---- b = b0 / ||b0||, thread t owns b[16t .. 16t+15] ----
    float b[16];
    {
        #pragma unroll
        for (int q4 = 0; q4 < 4; q4++) {
            const float4 v = *(const float4*)(br + tid*16 + q4*4);
            b[q4*4+0] = v.x; b[q4*4+1] = v.y; b[q4*4+2] = v.z; b[q4*4+3] = v.w;
        }
        float ss = 0.0f;
        #pragma unroll
        for (int i = 0; i < 16; i++) ss += b[i]*b[i];
        float tot = block_reduce_sum(ss, red);
        float inv = 1.0f / sqrtf(tot);
        #pragma unroll
        for (int i = 0; i < 16; i++) b[i] *= inv;
    }

    // ---- 100 power iterations + 1 final application ----
    for (int it = 0; it <= 100; ++it) {
        // pack b: buf0[n] = (b[2n], b[2n+1]), n = 8*tid + j
        #pragma unroll
        for (int j = 0; j < 8; ++j)
            buf0[SW(8*tid + j)] = make_float2(b[2*j], b[2*j + 1]);
        __syncthreads();

        // u = IFFT( Fc * FFT(b) )   (8192-pt real conv via 4096-pt CFFT)
        cfft4096<-1>(buf0, buf1, TW);             // -> buf1
        specA(buf1, Fc, TW);
        __syncthreads();
        cfft4096<+1>(buf1, buf0, TW);             // -> buf0 : packed u

        // w = first 8192 of IFFT_16384( Ft * FFT_16384([u,0]) )
        cfft8192<-1,true >(buf0, buf1, TW, false); // zero-pad fused; -> buf0
        specB(buf0, Ft, TW);
        __syncthreads();
        cfft8192<+1,false>(buf0, buf1, TW, true);  // lower half only; -> buf0

        float w_[16];
        #pragma unroll
        for (int j = 0; j < 8; ++j) {
            float2 v = buf0[SW(8*tid + j)];
            w_[2*j]     = v.x;
            w_[2*j + 1] = v.y;
        }

        if (it < 100) {
            float nb[16];
            float ss = 0.0f;
            #pragma unroll
            for (int i = 0; i < 16; i++) { nb[i] = b[i] - w_[i]; ss += nb[i]*nb[i]; }
            float tot = block_reduce_sum(ss, red);
            float inv = 1.0f / sqrtf(tot);
            #pragma unroll
            for (int i = 0; i < 16; i++) b[i] = nb[i] * inv;
        } else {
            float dp = 0.0f;
            #pragma unroll
            for (int i = 0; i < 16; i++) dp += b[i] * w_[i];
            float tot = block_reduce_sum(dp, red);
            if (tid == 0) g_sigma[row] = 1.0f - tot;   // sigma = b.(b-w) = 1 - b.w
        }
    }
}

__global__ void finalize_kernel(float* __restrict__ out)
{
    __shared__ float red[16];
    const int t = threadIdx.x;   // 512 threads
    float v = fabsf(g_sigma[t]);
    #pragma unroll
    for (int o = 16; o; o >>= 1) v += __shfl_down_sync(0xffffffffu, v, o);
    if ((t & 31) == 0) red[t >> 5] = v;
    __syncthreads();
    if (t < 16) {
        float s = red[t];
        #pragma unroll
        for (int o = 8; o; o >>= 1) s += __shfl_down_sync(0xffffu, s, o);
        if (t == 0) out[0] = s * (1.0f / 512.0f);
    }
}

extern "C" void kernel_launch(void* const* d_in, const int* in_sizes, int n_in,
                              void* d_out, int out_size)
{
    (void)in_sizes; (void)n_in; (void)out_size;
    const float* x    = (const float*)d_in[0];
    const float* circ = (const float*)d_in[1];
    const float* b0   = (const float*)d_in[2];

    cudaFuncSetAttribute(power_kernel,
                         cudaFuncAttributeMaxDynamicSharedMemorySize, SMEM_BYTES);
    power_kernel<<<NROW, BS, SMEM_BYTES>>>(x, circ, b0);
    finalize_kernel<<<1, 512>>>((float*)d_out);
}